// round 16
// baseline (speedup 1.0000x reference)
#include <cuda_runtime.h>
#include <math.h>

// Problem constants (fixed shapes per reference)
#define NN   2049          // max_seq_len
#define NOUT 2048          // output rows/cols = N-1
#define BB   16            // batch
// pos_w has 2*NN-1 = 4097 entries, ts_w has 129 entries.

// Device scratch (no allocations allowed in kernel_launch)
// LUT entry: {thr_INT (INT_MAX if none), vlo_bits, vhi_bits, 0}
__device__ int4 g_lut[128];
__device__ int  g_ts32[BB * NN];     // timestamps normalized to int32

// ---------------------------------------------------------------------------
// Genuine libdevice logf (immune to fast-math's logf->__logf substitution).
// ---------------------------------------------------------------------------
extern "C" __device__ float __nv_logf(float);

// Reference bucketization (verified bit-exact vs the jax reference in R9):
// XLA rewrites divide(log(x), 0.301f) -> multiply(log(x), rn(1/0.301f)).
__device__ __forceinline__ int bucket_ref(int v, float recip) {
    float r = __nv_logf((float)v);
    float q = __fmul_rn(r, recip);
    return (int)floorf(q);
}

// First INTEGER v in [1, 1e6] with bucket(v) >= k; INT_MAX if never reached.
__device__ __forceinline__ int first_int_ge(int k, float recip) {
    int lo = 1;
    int hi = 1000000;
    if (bucket_ref(hi, recip) < k) return 0x7FFFFFFF;
    while (lo < hi) {
        int mid = lo + ((hi - lo) >> 1);
        if (bucket_ref(mid, recip) >= k) hi = mid; else lo = mid + 1;
    }
    return lo;
}

// ---------------------------------------------------------------------------
// Fused prologue: blocks 0..15 normalize timestamps (dtype-robust), block 16
// builds the 128-cell threshold LUT with INTEGER thresholds.
// ---------------------------------------------------------------------------
__global__ void __launch_bounds__(256)
k_prep(const int* __restrict__ ts_raw, const float* __restrict__ ts_w) {
    const int tid = threadIdx.x;
    const int blk = blockIdx.x;

    if (blk < BB) {
        __shared__ int s_flag;
        if (tid == 0) s_flag = 0;
        __syncthreads();
        int local = 0;
        const int p0 = blk * 1024;           // pairs [p0, p0+1024) all < 16392
        for (int p = p0 + tid; p < p0 + 1024; p += 256)
            local |= ts_raw[2 * p + 1];
        if (local) atomicOr(&s_flag, 1);
        __syncthreads();

        const bool is64 = (s_flag == 0);
        const int base = blk * NN;
        if (is64) {
            for (int u = tid; u < NN; u += 256)
                g_ts32[base + u] = ts_raw[2 * (base + u)];
        } else {
            for (int u = tid; u < NN; u += 256)
                g_ts32[base + u] = ts_raw[base + u];
        }
    } else {
        const float recip = __fdiv_rn(1.0f, 0.301f);   // hoisted: one fdiv
        __shared__ int Tv[81];               // integer thresholds
        __shared__ int Tb[81];               // float-bit images (for cell math)
        if (tid <= 80) { Tv[tid] = 0x7FFFFFFF; Tb[tid] = 0x7F800000; }
        __syncthreads();
        if (tid >= 1 && tid < 80) {
            int v = first_int_ge(tid, recip);
            Tv[tid] = v;
            Tb[tid] = (v == 0x7FFFFFFF) ? 0x7F800000
                                        : __float_as_int((float)v);
        }
        __syncthreads();

        if (tid < 128) {
            int cellbase = (tid + 508) << 21;
            int cellend  = cellbase + (1 << 21);
            int blo = 0;
            #pragma unroll 1
            for (int k = 1; k < 80; ++k) blo += (Tb[k] <= cellbase) ? 1 : 0;
            int thr = 0x7FFFFFFF;            // integer threshold, none by default
            if (blo + 1 < 80 && Tb[blo + 1] < cellend) thr = Tv[blo + 1];
            int kv0 = min(blo, 128);
            int kv1 = min(blo + 1, 128);
            int4 e;
            e.x = thr;                       // INTEGER threshold
            e.y = __float_as_int(ts_w[kv0]);
            e.z = __float_as_int(ts_w[kv1]);
            e.w = 0;
            g_lut[tid] = e;
        }
    }
}

// ---------------------------------------------------------------------------
// Main kernel (R16): 2048 blocks x 16 consecutive rows, pos via 7-float
// register windows, tsi via broadcast int4 — as R15 — plus:
//  * INTEGER threshold compare (x >= L.x on ints; monotone-exact below 2^24)
//    -> no per-element I2F anywhere.
//  * TILE-level uniformity: dt monotone in j and row => range covered by the
//    two corners [tsi0 - tsv.w, tsi15 - tsv.x]. Same sign + same cell =>
//    ONE LUT entry serves all 64 elements, zero votes in the inner loop.
// out[b,i,j] = pos_w[j-i+2048] + ts_w[bucket(ts[b,i+1]-ts[b,j])]
// ---------------------------------------------------------------------------
__device__ __forceinline__ int cell_of_x(int x) {   // x >= 1
    return __float_as_int((float)x) >> 21;          // lutp is pre-offset by -508
}

__global__ void __launch_bounds__(512)
k_main(const float* __restrict__ pos_w, float* __restrict__ out) {
    __shared__ __align__(16) float s_pos[2068];   // 2064 used
    __shared__ __align__(16) int   s_ts[2052];    // 2049 used
    __shared__ __align__(16) int   s_tsi[16];     // ts[base_i+1 .. base_i+16]
    __shared__ __align__(16) int4  s_lut[128];

    const int tid = threadIdx.x;
    const int blk = blockIdx.x;              // 2048 blocks
    const int b   = blk >> 7;                // 128 blocks per batch
    const int rb  = blk & 127;
    const int base_i  = rb << 4;             // 16 consecutive rows
    const int s_start = 2048 - base_i - 16;  // pos_w staging origin (>= 0)

    for (int u = tid; u < 2064; u += 512) s_pos[u] = pos_w[s_start + u];
    for (int u = tid; u < 2049; u += 512) s_ts[u] = g_ts32[b * NN + u];
    if (tid < 16)  s_tsi[tid] = g_ts32[b * NN + base_i + tid + 1];
    if (tid < 128) s_lut[tid] = g_lut[tid];
    __syncthreads();

    const int j0 = tid << 2;                 // one float4 spans the row
    const int4 tsv = *(const int4*)&s_ts[j0];
    const int4* lutp = s_lut - 508;

    float* optr = out + (((size_t)(b * NOUT + base_i)) << 11) + j0;

    // ---- tile-level uniformity: corners of the dt range ----
    const int dtA = s_tsi[0]  - tsv.w;       // minimum dt over tile
    const int dtB = s_tsi[15] - tsv.x;       // maximum dt over tile
    const int xA  = max(abs(dtA), 1);
    const int xB  = max(abs(dtB), 1);
    const int cA  = cell_of_x(xA);
    const bool tile_uni = ((dtA ^ dtB) >= 0) & (cA == cell_of_x(xB));

    if (__all_sync(0xFFFFFFFFu, tile_uni)) {
        // ------- slim path: one LUT entry for all 64 elements -------
        const int4 L = lutp[cA];
        const int   thr = L.x;
        const float vlo = __int_as_float(L.y);
        const float vhi = __int_as_float(L.z);

        #pragma unroll
        for (int m = 0; m < 4; ++m) {
            const int4   tsq = *(const int4*)&s_tsi[m << 2];
            const float4 lo  = *(const float4*)&s_pos[j0 + 12 - (m << 2)];
            const float4 hi  = *(const float4*)&s_pos[j0 + 16 - (m << 2)];
            const float w[8] = {lo.x, lo.y, lo.z, lo.w, hi.x, hi.y, hi.z, hi.w};
            const int tsis[4] = {tsq.x, tsq.y, tsq.z, tsq.w};

            #pragma unroll
            for (int k = 0; k < 4; ++k) {
                const int tsi1 = tsis[k];
                const int x0 = max(abs(tsi1 - tsv.x), 1);
                const int x1 = max(abs(tsi1 - tsv.y), 1);
                const int x2 = max(abs(tsi1 - tsv.z), 1);
                const int x3 = max(abs(tsi1 - tsv.w), 1);
                float4 o;
                o.x = (x0 >= thr ? vhi : vlo) + w[4 - k];
                o.y = (x1 >= thr ? vhi : vlo) + w[5 - k];
                o.z = (x2 >= thr ? vhi : vlo) + w[6 - k];
                o.w = (x3 >= thr ? vhi : vlo) + w[7 - k];
                __stcs((float4*)optr, o);
                optr += NOUT;
            }
        }
    } else {
        // ------- per-row path (R15 logic, int compares) -------
        #pragma unroll
        for (int m = 0; m < 4; ++m) {
            const int4   tsq = *(const int4*)&s_tsi[m << 2];
            const float4 lo  = *(const float4*)&s_pos[j0 + 12 - (m << 2)];
            const float4 hi  = *(const float4*)&s_pos[j0 + 16 - (m << 2)];
            const float w[8] = {lo.x, lo.y, lo.z, lo.w, hi.x, hi.y, hi.z, hi.w};
            const int tsis[4] = {tsq.x, tsq.y, tsq.z, tsq.w};

            #pragma unroll
            for (int k = 0; k < 4; ++k) {
                const int tsi1 = tsis[k];
                const int dt0 = tsi1 - tsv.x;
                const int dt3 = tsi1 - tsv.w;
                const int x0 = max(abs(dt0), 1);
                const int x1 = max(abs(tsi1 - tsv.y), 1);
                const int x2 = max(abs(tsi1 - tsv.z), 1);
                const int x3 = max(abs(dt3), 1);
                const int c0 = cell_of_x(x0);
                const int c3 = cell_of_x(x3);

                float4 o;
                const bool same = (c0 == c3) & ((dt0 ^ dt3) >= 0);
                if (__all_sync(0xFFFFFFFFu, same)) {
                    const int4 L = lutp[c0];
                    o.x = __int_as_float(x0 >= L.x ? L.z : L.y);
                    o.y = __int_as_float(x1 >= L.x ? L.z : L.y);
                    o.z = __int_as_float(x2 >= L.x ? L.z : L.y);
                    o.w = __int_as_float(x3 >= L.x ? L.z : L.y);
                } else {
                    const int4 L0 = lutp[c0];
                    const int4 L1 = lutp[cell_of_x(x1)];
                    const int4 L2 = lutp[cell_of_x(x2)];
                    const int4 L3 = lutp[c3];
                    o.x = __int_as_float(x0 >= L0.x ? L0.z : L0.y);
                    o.y = __int_as_float(x1 >= L1.x ? L1.z : L1.y);
                    o.z = __int_as_float(x2 >= L2.x ? L2.z : L2.y);
                    o.w = __int_as_float(x3 >= L3.x ? L3.z : L3.y);
                }

                o.x += w[4 - k];
                o.y += w[5 - k];
                o.z += w[6 - k];
                o.w += w[7 - k];
                __stcs((float4*)optr, o);
                optr += NOUT;
            }
        }
    }
}

extern "C" void kernel_launch(void* const* d_in, const int* in_sizes, int n_in,
                              void* d_out, int out_size) {
    // Identify inputs by element count, not position (defensive).
    const void*  ts_raw = d_in[0];
    const float* posw   = (const float*)d_in[1];
    const float* tsw    = (const float*)d_in[2];
    for (int k = 0; k < n_in; ++k) {
        if (in_sizes[k] == BB * NN)         ts_raw = d_in[k];
        else if (in_sizes[k] == 2 * NN - 1) posw   = (const float*)d_in[k];
        else if (in_sizes[k] == 129)        tsw    = (const float*)d_in[k];
    }
    float* out = (float*)d_out;              // (16, 2048, 2048) f32

    k_prep<<<BB + 1, 256>>>((const int*)ts_raw, tsw);
    k_main<<<2048, 512>>>(posw, out);
}